// round 3
// baseline (speedup 1.0000x reference)
#include <cuda_runtime.h>
#include <math.h>

#define N_NODES 20000
#define E_EDGES 320000
#define F_IN    1024
#define H_MID   256
#define D_OUT   128
#define QKVS    512   // q|k|v|s concatenated
#define STAT_BLOCKS 256

// ---------------- scratch (static device globals; no allocations) ----------------
__device__ __align__(16) float  g_g[(size_t)N_NODES * H_MID];     // (x@Wgcn)*dinv[row]
__device__ __align__(16) float  g_h[(size_t)N_NODES * H_MID];     // post-GCN hidden
__device__ __align__(16) float  g_qkvs[(size_t)N_NODES * QKVS];   // [q|k|v|s] per node
__device__ __align__(16) float  g_alpha[E_EDGES];                 // raw attention logits
__device__ float  g_dinv[N_NODES];
__device__ int    g_degcnt[N_NODES];
__device__ int    g_fill[N_NODES];
__device__ int    g_rowptr[N_NODES + 1];
__device__ int    g_csrc[E_EDGES];
__device__ int    g_ceid[E_EDGES];
__device__ double g_part[STAT_BLOCKS][2];           // per-block sum, sumsq
__device__ float  g_stats[2];                       // mean, 3/std
__device__ __align__(16) float  g_Wcat[(size_t)H_MID * QKVS];
__device__ __align__(16) float  g_bcat[QKVS];

// ---------------- CSR build ----------------
__global__ void k_init() {
    int i = blockIdx.x * blockDim.x + threadIdx.x;
    if (i < N_NODES) { g_degcnt[i] = 0; g_fill[i] = 0; }
}

__global__ void k_hist(const int* __restrict__ ei) {
    int e = blockIdx.x * blockDim.x + threadIdx.x;
    if (e < E_EDGES) {
        int d = ei[E_EDGES + e];
        atomicAdd(&g_degcnt[d], 1);
    }
}

// single-block exclusive scan over 20000 counts; also computes dinv = rsqrt(indeg+1)
__global__ void k_scan() {
    const int n = N_NODES;
    const int PER = 20;                       // 1024*20 = 20480 >= 20000
    __shared__ int wsum[32];
    int tid = threadIdx.x, lane = tid & 31, wid = tid >> 5;
    int start = tid * PER;
    int cnt[PER];
    int local = 0;
#pragma unroll
    for (int u = 0; u < PER; u++) {
        int i = start + u;
        int c = (i < n) ? g_degcnt[i] : 0;
        cnt[u] = c; local += c;
    }
    int v = local;
#pragma unroll
    for (int d = 1; d < 32; d <<= 1) { int t = __shfl_up_sync(0xffffffffu, v, d); if (lane >= d) v += t; }
    if (lane == 31) wsum[wid] = v;
    __syncthreads();
    if (wid == 0) {
        int w = wsum[lane];
#pragma unroll
        for (int d = 1; d < 32; d <<= 1) { int t = __shfl_up_sync(0xffffffffu, w, d); if (lane >= d) w += t; }
        wsum[lane] = w;
    }
    __syncthreads();
    int excl = (v - local) + (wid > 0 ? wsum[wid - 1] : 0);
    int run = excl;
#pragma unroll
    for (int u = 0; u < PER; u++) {
        int i = start + u;
        if (i < n) {
            g_rowptr[i] = run;
            g_dinv[i] = rsqrtf((float)(cnt[u] + 1));  // +1 self loop
        }
        run += cnt[u];
    }
    if (tid == 1023) g_rowptr[n] = run;               // == E_EDGES
}

__global__ void k_csr(const int* __restrict__ ei) {
    int e = blockIdx.x * blockDim.x + threadIdx.x;
    if (e < E_EDGES) {
        int s = ei[e];
        int d = ei[E_EDGES + e];
        int pos = g_rowptr[d] + atomicAdd(&g_fill[d], 1);
        g_csrc[pos] = s;
        g_ceid[pos] = e;
    }
}

// ---------------- pack Wq|Wk|Wv|Ws -> [H_MID, 512] ----------------
__global__ void k_pack(const float* __restrict__ Wq, const float* __restrict__ Wk,
                       const float* __restrict__ Wv, const float* __restrict__ Ws,
                       const float* __restrict__ bq, const float* __restrict__ bk,
                       const float* __restrict__ bv, const float* __restrict__ bs) {
    int idx = blockIdx.x * blockDim.x + threadIdx.x;
    if (idx >= H_MID * QKVS) return;
    int k = idx >> 9;
    int c512 = idx & 511;
    int w = c512 >> 7;
    int c = c512 & 127;
    const float* W = (w == 0) ? Wq : (w == 1) ? Wk : (w == 2) ? Wv : Ws;
    g_Wcat[idx] = W[k * D_OUT + c];
    if (k == 0) {
        const float* b = (w == 0) ? bq : (w == 1) ? bk : (w == 2) ? bv : bs;
        g_bcat[c512] = b[c];
    }
}

// ---------------- fp32 SGEMM 128x128x8, 8x8 micro-tile ----------------
// MODE 0: C=g_g = (Aext @ Bext) * g_dinv[row]   (A=x, B=W_gcn, N=H_MID, K=F_IN)
// MODE 1: C=g_qkvs = (g_h @ g_Wcat) + g_bcat    (N=QKVS, K=H_MID)
template <int MODE>
__global__ __launch_bounds__(256)
void k_sgemm(const float* __restrict__ Aext, const float* __restrict__ Bext) {
    const int BM = 128, BN = 128, BK = 8, TM = 8, TN = 8;
    const float* A = (MODE == 0) ? Aext : (const float*)g_h;
    const float* B = (MODE == 0) ? Bext : (const float*)g_Wcat;
    float*       C = (MODE == 0) ? g_g : g_qkvs;
    const int M = N_NODES;
    const int N = (MODE == 0) ? H_MID : QKVS;
    const int K = (MODE == 0) ? F_IN : H_MID;

    __shared__ float As[BK][BM];
    __shared__ float Bs[BK][BN];
    int tid = threadIdx.x;
    int bx = blockIdx.x, by = blockIdx.y;
    int tx = tid & 15, ty = tid >> 4;

    float acc[TM][TN];
#pragma unroll
    for (int i = 0; i < TM; i++)
#pragma unroll
        for (int j = 0; j < TN; j++) acc[i][j] = 0.f;

    int a_row = tid >> 1, a_col = (tid & 1) * 4;
    int b_row = tid >> 5, b_col = (tid & 31) * 4;
    int rowA = by * BM + a_row;
    const float* Aptr = A + (size_t)rowA * K + a_col;
    const float* Bptr = B + (size_t)b_row * N + bx * BN + b_col;

    for (int k0 = 0; k0 < K; k0 += BK) {
        float4 av = (rowA < M) ? *(const float4*)(Aptr + k0) : make_float4(0.f, 0.f, 0.f, 0.f);
        As[a_col + 0][a_row] = av.x;
        As[a_col + 1][a_row] = av.y;
        As[a_col + 2][a_row] = av.z;
        As[a_col + 3][a_row] = av.w;
        float4 bvv = *(const float4*)(Bptr + (size_t)k0 * N);
        *(float4*)&Bs[b_row][b_col] = bvv;
        __syncthreads();
#pragma unroll
        for (int k = 0; k < BK; k++) {
            float ar[TM], br[TN];
#pragma unroll
            for (int i = 0; i < TM; i++) ar[i] = As[k][ty * TM + i];
#pragma unroll
            for (int j = 0; j < TN; j++) br[j] = Bs[k][tx * TN + j];
#pragma unroll
            for (int i = 0; i < TM; i++)
#pragma unroll
                for (int j = 0; j < TN; j++) acc[i][j] += ar[i] * br[j];
        }
        __syncthreads();
    }

#pragma unroll
    for (int i = 0; i < TM; i++) {
        int r = by * BM + ty * TM + i;
        if (r >= M) continue;
        float rs = (MODE == 0) ? g_dinv[r] : 1.f;
#pragma unroll
        for (int j = 0; j < TN; j += 4) {
            int c = bx * BN + tx * TN + j;
            float4 v;
            v.x = acc[i][j + 0] * rs + ((MODE == 1) ? g_bcat[c + 0] : 0.f);
            v.y = acc[i][j + 1] * rs + ((MODE == 1) ? g_bcat[c + 1] : 0.f);
            v.z = acc[i][j + 2] * rs + ((MODE == 1) ? g_bcat[c + 2] : 0.f);
            v.w = acc[i][j + 3] * rs + ((MODE == 1) ? g_bcat[c + 3] : 0.f);
            *(float4*)(C + (size_t)r * N + c) = v;
        }
    }
}

// ---------------- GCN aggregation: h = leakyrelu(dinv*(g_self + sum g_src) + b) ----------------
__global__ __launch_bounds__(H_MID)
void k_agg(const float* __restrict__ b_gcn) {
    int i = blockIdx.x;
    int f = threadIdx.x;
    float acc = g_g[(size_t)i * H_MID + f];   // self loop (g already has dinv[row])
    __shared__ int sj[H_MID];
    int s0 = g_rowptr[i], e0 = g_rowptr[i + 1];
    for (int base = s0; base < e0; base += H_MID) {
        int cnt = min(H_MID, e0 - base);
        if (f < cnt) sj[f] = g_csrc[base + f];
        __syncthreads();
        for (int p = 0; p < cnt; p++)
            acc += g_g[(size_t)sj[p] * H_MID + f];
        __syncthreads();
    }
    float v = g_dinv[i] * acc + b_gcn[f];
    g_h[(size_t)i * H_MID + f] = (v >= 0.f) ? v : 0.01f * v;
}

// ---------------- attention logits: alpha[e] = q[dst].k[src]/sqrt(128) ----------------
__global__ __launch_bounds__(256)
void k_alpha(const int* __restrict__ ei) {
    int warp = threadIdx.x >> 5, lane = threadIdx.x & 31;
    int e = blockIdx.x * 8 + warp;
    if (e >= E_EDGES) return;
    int s = ei[e], d = ei[E_EDGES + e];
    const float4* q = (const float4*)(g_qkvs + (size_t)d * QKVS);
    const float4* k = (const float4*)(g_qkvs + (size_t)s * QKVS + D_OUT);
    float4 a = q[lane], b = k[lane];
    float p = a.x * b.x + a.y * b.y + a.z * b.z + a.w * b.w;
#pragma unroll
    for (int o = 16; o; o >>= 1) p += __shfl_xor_sync(0xffffffffu, p, o);
    if (lane == 0) g_alpha[e] = p * 0.08838834764831845f;  // 1/sqrt(128)
}

// per-block partial sums (no atomics)
__global__ __launch_bounds__(256)
void k_stats() {
    double s = 0.0, s2 = 0.0;
    for (int i = blockIdx.x * blockDim.x + threadIdx.x; i < E_EDGES; i += STAT_BLOCKS * 256) {
        double a = (double)g_alpha[i];
        s += a; s2 += a * a;
    }
#pragma unroll
    for (int o = 16; o; o >>= 1) {
        s  += __shfl_down_sync(0xffffffffu, s,  o);
        s2 += __shfl_down_sync(0xffffffffu, s2, o);
    }
    __shared__ double ws[8], ws2[8];
    int lane = threadIdx.x & 31, wid = threadIdx.x >> 5;
    if (lane == 0) { ws[wid] = s; ws2[wid] = s2; }
    __syncthreads();
    if (threadIdx.x == 0) {
        double ts = 0.0, ts2 = 0.0;
        for (int w = 0; w < 8; w++) { ts += ws[w]; ts2 += ws2[w]; }
        g_part[blockIdx.x][0] = ts;
        g_part[blockIdx.x][1] = ts2;
    }
}

__global__ __launch_bounds__(STAT_BLOCKS)
void k_finalize() {
    int t = threadIdx.x;
    double s = g_part[t][0], s2 = g_part[t][1];
#pragma unroll
    for (int o = 16; o; o >>= 1) {
        s  += __shfl_down_sync(0xffffffffu, s,  o);
        s2 += __shfl_down_sync(0xffffffffu, s2, o);
    }
    __shared__ double ws[8], ws2[8];
    int lane = t & 31, wid = t >> 5;
    if (lane == 0) { ws[wid] = s; ws2[wid] = s2; }
    __syncthreads();
    if (t == 0) {
        double ts = 0.0, ts2 = 0.0;
        for (int w = 0; w < STAT_BLOCKS / 32; w++) { ts += ws[w]; ts2 += ws2[w]; }
        double En = (double)E_EDGES;
        double mean = ts / En;
        double var = (ts2 - En * mean * mean) / (En - 1.0);  // ddof=1
        g_stats[0] = (float)mean;
        g_stats[1] = (float)(3.0 / sqrt(var));               // SCALE_PARAM/std
    }
}

// ---------------- output: out[i] = s[i] + sum sigmoid(alpha)*v[src] ----------------
__global__ __launch_bounds__(D_OUT)
void k_out(float* __restrict__ out) {
    int i = blockIdx.x;
    int f = threadIdx.x;
    float mean = g_stats[0], sc = g_stats[1];
    float acc = g_qkvs[(size_t)i * QKVS + 384 + f];   // skip s = h@Ws + bs
    __shared__ int   sj[D_OUT];
    __shared__ float sa[D_OUT];
    int s0 = g_rowptr[i], e0 = g_rowptr[i + 1];
    for (int base = s0; base < e0; base += D_OUT) {
        int cnt = min(D_OUT, e0 - base);
        if (f < cnt) {
            sj[f] = g_csrc[base + f];
            float a = (g_alpha[g_ceid[base + f]] - mean) * sc;
            sa[f] = 1.0f / (1.0f + expf(-a));
        }
        __syncthreads();
        for (int p = 0; p < cnt; p++)
            acc += g_qkvs[(size_t)sj[p] * QKVS + 256 + f] * sa[p];
        __syncthreads();
    }
    out[(size_t)i * D_OUT + f] = acc;
}

// ---------------- launch ----------------
extern "C" void kernel_launch(void* const* d_in, const int* in_sizes, int n_in,
                              void* d_out, int out_size) {
    (void)in_sizes; (void)n_in; (void)out_size;
    const float* x     = (const float*)d_in[0];
    const int*   ei    = (const int*)d_in[1];     // int64 downcast to int32 by harness
    const float* W_gcn = (const float*)d_in[2];
    const float* b_gcn = (const float*)d_in[3];
    const float* Wq = (const float*)d_in[4],  *bq = (const float*)d_in[5];
    const float* Wk = (const float*)d_in[6],  *bk = (const float*)d_in[7];
    const float* Wv = (const float*)d_in[8],  *bv = (const float*)d_in[9];
    const float* Ws = (const float*)d_in[10], *bs = (const float*)d_in[11];
    float* out = (float*)d_out;

    k_init<<<(N_NODES + 255) / 256, 256>>>();
    k_hist<<<(E_EDGES + 255) / 256, 256>>>(ei);
    k_scan<<<1, 1024>>>();
    k_csr<<<(E_EDGES + 255) / 256, 256>>>(ei);
    k_pack<<<(H_MID * QKVS + 255) / 256, 256>>>(Wq, Wk, Wv, Ws, bq, bk, bv, bs);

    // g = (x @ W_gcn) * dinv[row]
    k_sgemm<0><<<dim3(H_MID / 128, (N_NODES + 127) / 128), 256>>>(x, W_gcn);

    k_agg<<<N_NODES, H_MID>>>(b_gcn);

    // qkvs = h @ Wcat + bcat
    k_sgemm<1><<<dim3(QKVS / 128, (N_NODES + 127) / 128), 256>>>(nullptr, nullptr);

    k_alpha<<<(E_EDGES + 7) / 8, 256>>>(ei);
    k_stats<<<STAT_BLOCKS, 256>>>();
    k_finalize<<<1, STAT_BLOCKS>>>();
    k_out<<<N_NODES, D_OUT>>>(out);
}

// round 7
// speedup vs baseline: 1.6752x; 1.6752x over previous
#include <cuda_runtime.h>
#include <cuda_bf16.h>
#include <math.h>
#include <stdint.h>

#define N_NODES 20000
#define E_EDGES 320000
#define F_IN    1024
#define H_MID   256
#define D_OUT   128
#define QKVS    512
#define STAT_BLOCKS 256
#define M_TILES ((N_NODES + 127) / 128)

// ---------------- scratch (static device globals; no allocations) ----------------
__device__ __align__(16) float  g_g[(size_t)N_NODES * H_MID];
__device__ __align__(16) float  g_h[(size_t)N_NODES * H_MID];
__device__ __align__(16) float  g_qkvs[(size_t)N_NODES * QKVS];
__device__ __align__(16) float  g_alpha[E_EDGES];
__device__ float  g_dinv[N_NODES];
__device__ int    g_degcnt[N_NODES];
__device__ int    g_fill[N_NODES];
__device__ int    g_rowptr[N_NODES + 1];
__device__ int    g_csrc[E_EDGES];
__device__ int    g_ceid[E_EDGES];
__device__ double g_part[STAT_BLOCKS][2];
__device__ float  g_stats[2];
__device__ __align__(16) float  g_bcat[QKVS];
// bf16 split operands (weights transposed to [N][K] K-major rows)
__device__ __align__(16) __nv_bfloat16 g_Ahi[(size_t)N_NODES * F_IN];
__device__ __align__(16) __nv_bfloat16 g_Alo[(size_t)N_NODES * F_IN];
__device__ __align__(16) __nv_bfloat16 g_B1hi[(size_t)H_MID * F_IN];
__device__ __align__(16) __nv_bfloat16 g_B1lo[(size_t)H_MID * F_IN];
__device__ __align__(16) __nv_bfloat16 g_Hhi[(size_t)N_NODES * H_MID];
__device__ __align__(16) __nv_bfloat16 g_Hlo[(size_t)N_NODES * H_MID];
__device__ __align__(16) __nv_bfloat16 g_B2hi[(size_t)QKVS * H_MID];
__device__ __align__(16) __nv_bfloat16 g_B2lo[(size_t)QKVS * H_MID];

// ---------------- helpers ----------------
__device__ __forceinline__ uint32_t smem_u32(const void* p) {
    uint32_t a;
    asm("{ .reg .u64 t; cvta.to.shared.u64 t, %1; cvt.u32.u64 %0, t; }" : "=r"(a) : "l"(p));
    return a;
}
__device__ __forceinline__ void mma16816(float* c, const uint32_t* a, const uint32_t* b) {
    asm volatile(
        "mma.sync.aligned.m16n8k16.row.col.f32.bf16.bf16.f32 "
        "{%0,%1,%2,%3}, {%4,%5,%6,%7}, {%8,%9}, {%0,%1,%2,%3};"
        : "+f"(c[0]), "+f"(c[1]), "+f"(c[2]), "+f"(c[3])
        : "r"(a[0]), "r"(a[1]), "r"(a[2]), "r"(a[3]), "r"(b[0]), "r"(b[1]));
}
__device__ __forceinline__ void ldm4(uint32_t* r, uint32_t addr) {
    asm volatile("ldmatrix.sync.aligned.m8n8.x4.shared.b16 {%0,%1,%2,%3}, [%4];"
        : "=r"(r[0]), "=r"(r[1]), "=r"(r[2]), "=r"(r[3]) : "r"(addr) : "memory");
}

// ---------------- CSR build ----------------
__global__ void k_init() {
    int i = blockIdx.x * blockDim.x + threadIdx.x;
    if (i < N_NODES) { g_degcnt[i] = 0; g_fill[i] = 0; }
}

__global__ void k_hist(const int* __restrict__ ei) {
    int e = blockIdx.x * blockDim.x + threadIdx.x;
    if (e < E_EDGES) atomicAdd(&g_degcnt[ei[E_EDGES + e]], 1);
}

__global__ void k_scan() {
    const int n = N_NODES;
    const int PER = 20;
    __shared__ int wsum[32];
    int tid = threadIdx.x, lane = tid & 31, wid = tid >> 5;
    int start = tid * PER;
    int cnt[PER];
    int local = 0;
#pragma unroll
    for (int u = 0; u < PER; u++) {
        int i = start + u;
        int c = (i < n) ? g_degcnt[i] : 0;
        cnt[u] = c; local += c;
    }
    int v = local;
#pragma unroll
    for (int d = 1; d < 32; d <<= 1) { int t = __shfl_up_sync(0xffffffffu, v, d); if (lane >= d) v += t; }
    if (lane == 31) wsum[wid] = v;
    __syncthreads();
    if (wid == 0) {
        int w = wsum[lane];
#pragma unroll
        for (int d = 1; d < 32; d <<= 1) { int t = __shfl_up_sync(0xffffffffu, w, d); if (lane >= d) w += t; }
        wsum[lane] = w;
    }
    __syncthreads();
    int excl = (v - local) + (wid > 0 ? wsum[wid - 1] : 0);
    int run = excl;
#pragma unroll
    for (int u = 0; u < PER; u++) {
        int i = start + u;
        if (i < n) {
            g_rowptr[i] = run;
            g_dinv[i] = rsqrtf((float)(cnt[u] + 1));
        }
        run += cnt[u];
    }
    if (tid == 1023) g_rowptr[n] = run;
}

__global__ void k_csr(const int* __restrict__ ei) {
    int e = blockIdx.x * blockDim.x + threadIdx.x;
    if (e < E_EDGES) {
        int s = ei[e];
        int d = ei[E_EDGES + e];
        int pos = g_rowptr[d] + atomicAdd(&g_fill[d], 1);
        g_csrc[pos] = s;
        g_ceid[pos] = e;
    }
}

// ---------------- conversions (fp32 -> bf16 hi/lo split) ----------------
__device__ __forceinline__ void split2(float a, float b, __nv_bfloat162& h, __nv_bfloat162& l) {
    __nv_bfloat16 ha = __float2bfloat16_rn(a);
    __nv_bfloat16 hb = __float2bfloat16_rn(b);
    h.x = ha; h.y = hb;
    l.x = __float2bfloat16_rn(a - __bfloat162float(ha));
    l.y = __float2bfloat16_rn(b - __bfloat162float(hb));
}

__global__ void k_convA(const float* __restrict__ X) {
    size_t i = (size_t)blockIdx.x * 256 + threadIdx.x;
    if (i >= (size_t)N_NODES * F_IN / 4) return;
    float4 v = ((const float4*)X)[i];
    __nv_bfloat162 h0, l0, h1, l1;
    split2(v.x, v.y, h0, l0);
    split2(v.z, v.w, h1, l1);
    ((__nv_bfloat162*)g_Ahi)[2 * i] = h0;
    ((__nv_bfloat162*)g_Ahi)[2 * i + 1] = h1;
    ((__nv_bfloat162*)g_Alo)[2 * i] = l0;
    ((__nv_bfloat162*)g_Alo)[2 * i + 1] = l1;
}

__global__ void k_convH() {
    size_t i = (size_t)blockIdx.x * 256 + threadIdx.x;
    if (i >= (size_t)N_NODES * H_MID / 4) return;
    float4 v = ((const float4*)g_h)[i];
    __nv_bfloat162 h0, l0, h1, l1;
    split2(v.x, v.y, h0, l0);
    split2(v.z, v.w, h1, l1);
    ((__nv_bfloat162*)g_Hhi)[2 * i] = h0;
    ((__nv_bfloat162*)g_Hhi)[2 * i + 1] = h1;
    ((__nv_bfloat162*)g_Hlo)[2 * i] = l0;
    ((__nv_bfloat162*)g_Hlo)[2 * i + 1] = l1;
}

// W_gcn[1024,256] -> B1 [256][1024]
__global__ void k_convBW(const float* __restrict__ Wg) {
    int idx = blockIdx.x * blockDim.x + threadIdx.x;
    if (idx >= H_MID * F_IN) return;
    int n = idx >> 10, k = idx & 1023;
    float v = Wg[(size_t)k * H_MID + n];
    __nv_bfloat16 h = __float2bfloat16_rn(v);
    g_B1hi[idx] = h;
    g_B1lo[idx] = __float2bfloat16_rn(v - __bfloat162float(h));
}

// Wq|Wk|Wv|Ws [256,128] -> B2 [512][256] + bcat
__global__ void k_packB2(const float* __restrict__ Wq, const float* __restrict__ Wk,
                         const float* __restrict__ Wv, const float* __restrict__ Ws,
                         const float* __restrict__ bq, const float* __restrict__ bk,
                         const float* __restrict__ bv, const float* __restrict__ bs) {
    int idx = blockIdx.x * blockDim.x + threadIdx.x;
    if (idx >= QKVS * H_MID) return;
    int n = idx >> 8, k = idx & 255;
    int w = n >> 7, c = n & 127;
    const float* W = (w == 0) ? Wq : (w == 1) ? Wk : (w == 2) ? Wv : Ws;
    float v = W[(size_t)k * D_OUT + c];
    __nv_bfloat16 h = __float2bfloat16_rn(v);
    g_B2hi[idx] = h;
    g_B2lo[idx] = __float2bfloat16_rn(v - __bfloat162float(h));
    if (idx < QKVS) {
        int nn = idx, ww = nn >> 7, cc = nn & 127;
        const float* b = (ww == 0) ? bq : (ww == 1) ? bk : (ww == 2) ? bv : bs;
        g_bcat[nn] = b[cc];
    }
}

// ---------------- split-bf16 GEMM via mma.sync (HMMA, plain PTX) ----------------
// All operands are __device__ globals referenced IN DEVICE CODE (never passed
// as kernel args from host — host-side &g_X is the shadow symbol and on GB300
// ATS silently reads host zeros instead of faulting).
// MODE 0: g_g = (x @ W_gcn) * dinv[row]   A=g_Ahi/lo [N][1024], B=g_B1 [256][1024]
// MODE 1: g_qkvs = h @ Wcat + bcat        A=g_Hhi/lo [N][256],  B=g_B2 [512][256]
#define SPAD 24

template <int MODE>
__global__ __launch_bounds__(256)
void k_mmagemm() {
    const int K_TOT = (MODE == 0) ? F_IN : H_MID;
    const __nv_bfloat16* Ahi = (MODE == 0) ? g_Ahi : g_Hhi;
    const __nv_bfloat16* Alo = (MODE == 0) ? g_Alo : g_Hlo;
    const __nv_bfloat16* Bhi = (MODE == 0) ? g_B1hi : g_B2hi;
    const __nv_bfloat16* Blo = (MODE == 0) ? g_B1lo : g_B2lo;

    __shared__ __align__(16) __nv_bfloat16 sAh[128 * SPAD], sAl[128 * SPAD];
    __shared__ __align__(16) __nv_bfloat16 sBh[128 * SPAD], sBl[128 * SPAD];

    int tid = threadIdx.x, wid = tid >> 5, lane = tid & 31;
    int m0 = blockIdx.x * 128, n0 = blockIdx.y * 128;
    int wm = wid & 3, wn = wid >> 2;          // warp grid 4(m) x 2(n); warp tile 32x64

    int lrow = tid >> 1, lhalf = (tid & 1) << 3;
    const int NCH = K_TOT / 16;
    int arow = m0 + lrow;
    bool aok = arow < N_NODES;
    const __nv_bfloat16* pAh = Ahi + (size_t)arow * K_TOT + lhalf;
    const __nv_bfloat16* pAl = Alo + (size_t)arow * K_TOT + lhalf;
    const __nv_bfloat16* pBh = Bhi + (size_t)(n0 + lrow) * K_TOT + lhalf;
    const __nv_bfloat16* pBl = Blo + (size_t)(n0 + lrow) * K_TOT + lhalf;

    uint4 z4 = make_uint4(0, 0, 0, 0);
    uint4 vah = aok ? *(const uint4*)pAh : z4;
    uint4 val_ = aok ? *(const uint4*)pAl : z4;
    uint4 vbh = *(const uint4*)pBh;
    uint4 vbl = *(const uint4*)pBl;

    float acc[2][8][4];
#pragma unroll
    for (int a = 0; a < 2; a++)
#pragma unroll
        for (int b = 0; b < 8; b++)
#pragma unroll
            for (int c = 0; c < 4; c++) acc[a][b][c] = 0.f;

    uint32_t baseAh = smem_u32(sAh), baseAl = smem_u32(sAl);
    uint32_t baseBh = smem_u32(sBh), baseBl = smem_u32(sBl);
    int soff = lrow * SPAD + lhalf;

    int g8 = lane >> 3, w8 = lane & 7;
    uint32_t a_off = (uint32_t)((((((g8 & 1) << 3) + w8) + wm * 32) * SPAD + ((g8 >> 1) << 3)) * 2);
    uint32_t b_off = (uint32_t)((((((g8 >> 1) << 3) + w8) + wn * 64) * SPAD + ((g8 & 1) << 3)) * 2);

    for (int c = 0; c < NCH; c++) {
        *(uint4*)&sAh[soff] = vah;
        *(uint4*)&sAl[soff] = val_;
        *(uint4*)&sBh[soff] = vbh;
        *(uint4*)&sBl[soff] = vbl;
        __syncthreads();
        if (c + 1 < NCH) {
            int k0 = (c + 1) * 16;
            vah = aok ? *(const uint4*)(pAh + k0) : z4;
            val_ = aok ? *(const uint4*)(pAl + k0) : z4;
            vbh = *(const uint4*)(pBh + k0);
            vbl = *(const uint4*)(pBl + k0);
        }
        uint32_t ah[2][4], al[2][4], bh[4][4], bl[4][4];
#pragma unroll
        for (int mb = 0; mb < 2; mb++) {
            ldm4(ah[mb], baseAh + a_off + mb * 16 * SPAD * 2);
            ldm4(al[mb], baseAl + a_off + mb * 16 * SPAD * 2);
        }
#pragma unroll
        for (int q = 0; q < 4; q++) {
            ldm4(bh[q], baseBh + b_off + q * 16 * SPAD * 2);
            ldm4(bl[q], baseBl + b_off + q * 16 * SPAD * 2);
        }
#pragma unroll
        for (int mb = 0; mb < 2; mb++)
#pragma unroll
            for (int q = 0; q < 4; q++)
#pragma unroll
                for (int hh = 0; hh < 2; hh++) {
                    float* ca = acc[mb][q * 2 + hh];
                    mma16816(ca, ah[mb], &bh[q][hh * 2]);
                    mma16816(ca, al[mb], &bh[q][hh * 2]);
                    mma16816(ca, ah[mb], &bl[q][hh * 2]);
                }
        __syncthreads();
    }

    const int CS = (MODE == 0) ? H_MID : QKVS;
    float* Cp = (MODE == 0) ? g_g : g_qkvs;
#pragma unroll
    for (int mb = 0; mb < 2; mb++) {
        int rbase = m0 + wm * 32 + mb * 16 + (lane >> 2);
#pragma unroll
        for (int hf = 0; hf < 2; hf++) {
            int r = rbase + hf * 8;
            if (r >= N_NODES) continue;
            float rs = (MODE == 0) ? g_dinv[r] : 1.f;
#pragma unroll
            for (int n8 = 0; n8 < 8; n8++) {
                int col = n0 + wn * 64 + n8 * 8 + ((lane & 3) << 1);
                float v0 = acc[mb][n8][hf * 2 + 0];
                float v1 = acc[mb][n8][hf * 2 + 1];
                if (MODE == 0) { v0 *= rs; v1 *= rs; }
                else { v0 += g_bcat[col]; v1 += g_bcat[col + 1]; }
                float2 o; o.x = v0; o.y = v1;
                *(float2*)(Cp + (size_t)r * CS + col) = o;
            }
        }
    }
}

// ---------------- GCN aggregation ----------------
__global__ __launch_bounds__(H_MID)
void k_agg(const float* __restrict__ b_gcn) {
    int i = blockIdx.x;
    int f = threadIdx.x;
    float acc = g_g[(size_t)i * H_MID + f];
    __shared__ int sj[H_MID];
    int s0 = g_rowptr[i], e0 = g_rowptr[i + 1];
    for (int base = s0; base < e0; base += H_MID) {
        int cnt = min(H_MID, e0 - base);
        if (f < cnt) sj[f] = g_csrc[base + f];
        __syncthreads();
        for (int p = 0; p < cnt; p++)
            acc += g_g[(size_t)sj[p] * H_MID + f];
        __syncthreads();
    }
    float v = g_dinv[i] * acc + b_gcn[f];
    g_h[(size_t)i * H_MID + f] = (v >= 0.f) ? v : 0.01f * v;
}

// ---------------- attention logits ----------------
__global__ __launch_bounds__(256)
void k_alpha(const int* __restrict__ ei) {
    int warp = threadIdx.x >> 5, lane = threadIdx.x & 31;
    int e = blockIdx.x * 8 + warp;
    if (e >= E_EDGES) return;
    int s = ei[e], d = ei[E_EDGES + e];
    const float4* q = (const float4*)(g_qkvs + (size_t)d * QKVS);
    const float4* k = (const float4*)(g_qkvs + (size_t)s * QKVS + D_OUT);
    float4 a = q[lane], b = k[lane];
    float p = a.x * b.x + a.y * b.y + a.z * b.z + a.w * b.w;
#pragma unroll
    for (int o = 16; o; o >>= 1) p += __shfl_xor_sync(0xffffffffu, p, o);
    if (lane == 0) g_alpha[e] = p * 0.08838834764831845f;
}

__global__ __launch_bounds__(256)
void k_stats() {
    double s = 0.0, s2 = 0.0;
    for (int i = blockIdx.x * blockDim.x + threadIdx.x; i < E_EDGES; i += STAT_BLOCKS * 256) {
        double a = (double)g_alpha[i];
        s += a; s2 += a * a;
    }
#pragma unroll
    for (int o = 16; o; o >>= 1) {
        s  += __shfl_down_sync(0xffffffffu, s,  o);
        s2 += __shfl_down_sync(0xffffffffu, s2, o);
    }
    __shared__ double ws[8], ws2[8];
    int lane = threadIdx.x & 31, wid = threadIdx.x >> 5;
    if (lane == 0) { ws[wid] = s; ws2[wid] = s2; }
    __syncthreads();
    if (threadIdx.x == 0) {
        double ts = 0.0, ts2 = 0.0;
        for (int w = 0; w < 8; w++) { ts += ws[w]; ts2 += ws2[w]; }
        g_part[blockIdx.x][0] = ts;
        g_part[blockIdx.x][1] = ts2;
    }
}

__global__ __launch_bounds__(STAT_BLOCKS)
void k_finalize() {
    int t = threadIdx.x;
    double s = g_part[t][0], s2 = g_part[t][1];
#pragma unroll
    for (int o = 16; o; o >>= 1) {
        s  += __shfl_down_sync(0xffffffffu, s,  o);
        s2 += __shfl_down_sync(0xffffffffu, s2, o);
    }
    __shared__ double ws[8], ws2[8];
    int lane = t & 31, wid = t >> 5;
    if (lane == 0) { ws[wid] = s; ws2[wid] = s2; }
    __syncthreads();
    if (t == 0) {
        double ts = 0.0, ts2 = 0.0;
        for (int w = 0; w < STAT_BLOCKS / 32; w++) { ts += ws[w]; ts2 += ws2[w]; }
        double En = (double)E_EDGES;
        double mean = ts / En;
        double var = (ts2 - En * mean * mean) / (En - 1.0);
        g_stats[0] = (float)mean;
        g_stats[1] = (float)(3.0 / sqrt(var));
    }
}

// ---------------- output ----------------
__global__ __launch_bounds__(D_OUT)
void k_out(float* __restrict__ out) {
    int i = blockIdx.x;
    int f = threadIdx.x;
    float mean = g_stats[0], sc = g_stats[1];
    float acc = g_qkvs[(size_t)i * QKVS + 384 + f];
    __shared__ int   sj[D_OUT];
    __shared__ float sa[D_OUT];
    int s0 = g_rowptr[i], e0 = g_rowptr[i + 1];
    for (int base = s0; base < e0; base += D_OUT) {
        int cnt = min(D_OUT, e0 - base);
        if (f < cnt) {
            sj[f] = g_csrc[base + f];
            float a = (g_alpha[g_ceid[base + f]] - mean) * sc;
            sa[f] = 1.0f / (1.0f + expf(-a));
        }
        __syncthreads();
        for (int p = 0; p < cnt; p++)
            acc += g_qkvs[(size_t)sj[p] * QKVS + 256 + f] * sa[p];
        __syncthreads();
    }
    out[(size_t)i * D_OUT + f] = acc;
}

// ---------------- launch ----------------
extern "C" void kernel_launch(void* const* d_in, const int* in_sizes, int n_in,
                              void* d_out, int out_size) {
    (void)in_sizes; (void)n_in; (void)out_size;
    const float* x     = (const float*)d_in[0];
    const int*   ei    = (const int*)d_in[1];
    const float* W_gcn = (const float*)d_in[2];
    const float* b_gcn = (const float*)d_in[3];
    const float* Wq = (const float*)d_in[4],  *bq = (const float*)d_in[5];
    const float* Wk = (const float*)d_in[6],  *bk = (const float*)d_in[7];
    const float* Wv = (const float*)d_in[8],  *bv = (const float*)d_in[9];
    const float* Ws = (const float*)d_in[10], *bs = (const float*)d_in[11];
    float* out = (float*)d_out;

    k_init<<<(N_NODES + 255) / 256, 256>>>();
    k_hist<<<(E_EDGES + 255) / 256, 256>>>(ei);
    k_scan<<<1, 1024>>>();
    k_csr<<<(E_EDGES + 255) / 256, 256>>>(ei);

    k_convA<<<(int)(((size_t)N_NODES * F_IN / 4 + 255) / 256), 256>>>(x);
    k_convBW<<<(H_MID * F_IN + 255) / 256, 256>>>(W_gcn);
    k_packB2<<<(QKVS * H_MID + 255) / 256, 256>>>(Wq, Wk, Wv, Ws, bq, bk, bv, bs);

    // g = (x @ W_gcn) * dinv[row]
    k_mmagemm<0><<<dim3(M_TILES, 2), 256>>>();

    k_agg<<<N_NODES, H_MID>>>(b_gcn);
    k_convH<<<(int)(((size_t)N_NODES * H_MID / 4 + 255) / 256), 256>>>();

    // qkvs = h @ Wcat + bcat
    k_mmagemm<1><<<dim3(M_TILES, 4), 256>>>();

    k_alpha<<<(E_EDGES + 7) / 8, 256>>>(ei);
    k_stats<<<STAT_BLOCKS, 256>>>();
    k_finalize<<<1, STAT_BLOCKS>>>();
    k_out<<<N_NODES, D_OUT>>>(out);
}